// round 2
// baseline (speedup 1.0000x reference)
#include <cuda_runtime.h>
#include <math.h>
#include <stdint.h>

// Problem dims
#define T_DIM 4096
#define B_DIM 16
#define H_DIM 256
#define D_DIM 256
#define M_DIM (T_DIM * B_DIM)        // 65536 rows (t*B + b)
#define N1 (2 * H_DIM)               // 512: [re | im] packed Bu / h columns
#define NCHUNK 32
#define LCH (T_DIM / NCHUNK)         // 128 timesteps per chunk
#define CS (NCHUNK * B_DIM * H_DIM)  // 131072 chunk-lane summaries

// -------- device scratch (no runtime allocation allowed) --------
__device__ float g_Bu[(long long)M_DIM * N1];   // 128 MB: Bu, then overwritten in-place by h
__device__ float g_GB[N1 * D_DIM];              // [n][d]: gamma-scaled B_re / B_im stacked
__device__ float g_CC[D_DIM * N1];              // [d][k]: [C_re | -C_im]
__device__ float g_lam[2 * H_DIM];              // lam_re, lam_im
__device__ float g_gamma[H_DIM];
__device__ unsigned char g_flags[M_DIM];        // starts per (t,b)
__device__ float g_csum[5 * CS];                // chunk summaries SoA: Ar,Ai,br,bi,d
__device__ float g_carry[2 * CS];               // chunk carry-in states SoA: re, im
__device__ int g_mode;                          // starts dtype: 0=u8, 1=int32, 2=float32

// -------- starts dtype detection --------
__global__ void k_detect(const unsigned char* __restrict__ s, int nbytes) {
    __shared__ int sh_gt1, sh_nm4;
    if (threadIdx.x == 0) { sh_gt1 = 0; sh_nm4 = 0; }
    __syncthreads();
    int gt1 = 0, nm4 = 0;
    for (int i = threadIdx.x; i < nbytes; i += blockDim.x) {
        unsigned char v = s[i];
        if (v > 1) gt1 = 1;
        if (v != 0 && (i & 3) != 0) nm4 = 1;
    }
    if (gt1) atomicOr(&sh_gt1, 1);
    if (nm4) atomicOr(&sh_nm4, 1);
    __syncthreads();
    if (threadIdx.x == 0) g_mode = sh_gt1 ? 2 : (sh_nm4 ? 0 : 1);
}

__global__ void k_flags(const void* __restrict__ s) {
    int i = blockIdx.x * blockDim.x + threadIdx.x;
    if (i >= M_DIM) return;
    int m = g_mode;
    unsigned char f;
    if (m == 0)       f = ((const unsigned char*)s)[i] != 0;
    else if (m == 1)  f = ((const int*)s)[i] != 0;
    else              f = ((const float*)s)[i] != 0.0f;
    g_flags[i] = f;
}

// -------- parameter prep --------
__global__ void k_lam(const float* __restrict__ nu_log, const float* __restrict__ theta_log) {
    int h = threadIdx.x;
    if (h >= H_DIM) return;
    float nu = expf(nu_log[h]);
    float th = expf(theta_log[h]);
    float mag = expf(-nu);
    float lr = mag * cosf(th);
    float li = mag * sinf(th);
    float g2 = 1.0f - mag * mag;
    g_lam[h] = lr;
    g_lam[H_DIM + h] = li;
    g_gamma[h] = sqrtf(fmaxf(g2, 1e-8f));
}

__global__ void k_gb(const float* __restrict__ B_re, const float* __restrict__ B_im) {
    int i = blockIdx.x * blockDim.x + threadIdx.x;  // N1*D_DIM
    if (i >= N1 * D_DIM) return;
    int n = i >> 8;        // row in [0,512)
    int d = i & 255;
    int h = n & 255;
    float g = g_gamma[h];
    float v = (n < H_DIM) ? B_re[h * D_DIM + d] : B_im[h * D_DIM + d];
    g_GB[i] = v * g;
}

__global__ void k_cc(const float* __restrict__ C_re, const float* __restrict__ C_im) {
    int i = blockIdx.x * blockDim.x + threadIdx.x;  // D_DIM*N1
    if (i >= D_DIM * N1) return;
    int d = i >> 9;        // row in [0,256)
    int k = i & 511;
    g_CC[i] = (k < H_DIM) ? C_re[d * H_DIM + k] : -C_im[d * H_DIM + (k - H_DIM)];
}

// -------- fp32 SIMT GEMM: C[M,N] = A[M,K] @ B[N,K]^T  (+ optional D*x epilogue) --------
#define BM 128
#define BN 128
#define BK 8

__global__ __launch_bounds__(256) void sgemm_nt(
    const float* __restrict__ A, const float* __restrict__ Bm,
    float* __restrict__ C, int M, int N, int K,
    const float* __restrict__ Dv, const float* __restrict__ X)
{
    __shared__ float As[BK][BM];
    __shared__ float Bs[BK][BN];

    int tid = threadIdx.x;
    int bm = blockIdx.y, bn = blockIdx.x;
    int tx = tid & 15, ty = tid >> 4;

    float acc[8][8];
    #pragma unroll
    for (int i = 0; i < 8; i++)
        #pragma unroll
        for (int j = 0; j < 8; j++) acc[i][j] = 0.0f;

    int lrow = tid >> 1;            // 0..127
    int lc4 = (tid & 1) * 4;        // 0 or 4
    const float* Ab = A + (long long)(bm * BM + lrow) * K + lc4;
    const float* Bb = Bm + (long long)(bn * BN + lrow) * K + lc4;

    for (int k0 = 0; k0 < K; k0 += BK) {
        float4 av = *(const float4*)(Ab + k0);
        float4 bv = *(const float4*)(Bb + k0);
        As[lc4 + 0][lrow] = av.x; As[lc4 + 1][lrow] = av.y;
        As[lc4 + 2][lrow] = av.z; As[lc4 + 3][lrow] = av.w;
        Bs[lc4 + 0][lrow] = bv.x; Bs[lc4 + 1][lrow] = bv.y;
        Bs[lc4 + 2][lrow] = bv.z; Bs[lc4 + 3][lrow] = bv.w;
        __syncthreads();

        #pragma unroll
        for (int kk = 0; kk < BK; kk++) {
            float4 a0 = *(const float4*)&As[kk][ty * 8];
            float4 a1 = *(const float4*)&As[kk][ty * 8 + 4];
            float4 b0 = *(const float4*)&Bs[kk][tx * 8];
            float4 b1 = *(const float4*)&Bs[kk][tx * 8 + 4];
            float ra[8] = {a0.x, a0.y, a0.z, a0.w, a1.x, a1.y, a1.z, a1.w};
            float rb[8] = {b0.x, b0.y, b0.z, b0.w, b1.x, b1.y, b1.z, b1.w};
            #pragma unroll
            for (int i = 0; i < 8; i++)
                #pragma unroll
                for (int j = 0; j < 8; j++)
                    acc[i][j] = fmaf(ra[i], rb[j], acc[i][j]);
        }
        __syncthreads();
    }

    int row0 = bm * BM + ty * 8;
    int col0 = bn * BN + tx * 8;
    #pragma unroll
    for (int i = 0; i < 8; i++) {
        int row = row0 + i;
        float* crow = C + (long long)row * N + col0;
        if (Dv) {
            const float* xrow = X + (long long)row * N + col0;
            #pragma unroll
            for (int j = 0; j < 8; j++)
                acc[i][j] = fmaf(Dv[col0 + j], xrow[j], acc[i][j]);
        }
        *(float4*)crow = make_float4(acc[i][0], acc[i][1], acc[i][2], acc[i][3]);
        *(float4*)(crow + 4) = make_float4(acc[i][4], acc[i][5], acc[i][6], acc[i][7]);
    }
}

// -------- segmented scan, 3 phases --------
// op: element_t = (A=Lam, b=Bu_t, d=start_t); combine(lhs,rhs): if d_rhs reset.

__global__ void scan_p1() {
    int tg = blockIdx.x * blockDim.x + threadIdx.x;  // NCHUNK*4096
    if (tg >= CS) return;
    int h = tg & 255;
    int b = (tg >> 8) & 15;
    int c = tg >> 12;
    float lr = g_lam[h], li = g_lam[H_DIM + h];
    float Ar = 1.0f, Ai = 0.0f, br = 0.0f, bi = 0.0f;
    float dAny = 0.0f;
    int t0 = c * LCH;
    for (int t = t0; t < t0 + LCH; t++) {
        int row = t * B_DIM + b;
        const float* p = g_Bu + (long long)row * N1;
        float ur = p[h], ui = p[H_DIM + h];
        if (g_flags[row]) {
            Ar = lr; Ai = li; br = ur; bi = ui; dAny = 1.0f;
        } else {
            float nAr = lr * Ar - li * Ai;
            Ai = lr * Ai + li * Ar; Ar = nAr;
            float nbr = lr * br - li * bi + ur;
            bi = lr * bi + li * br + ui; br = nbr;
        }
    }
    int idx = c * 4096 + b * 256 + h;
    g_csum[0 * CS + idx] = Ar;
    g_csum[1 * CS + idx] = Ai;
    g_csum[2 * CS + idx] = br;
    g_csum[3 * CS + idx] = bi;
    g_csum[4 * CS + idx] = dAny;
}

__global__ void scan_p2(const float* __restrict__ st_re, const float* __restrict__ st_im) {
    int bh = blockIdx.x * blockDim.x + threadIdx.x;  // 4096 = b*256+h
    if (bh >= B_DIM * H_DIM) return;
    float sr = st_re[bh], si = st_im[bh];
    for (int c = 0; c < NCHUNK; c++) {
        int idx = c * 4096 + bh;
        g_carry[0 * CS + idx] = sr;
        g_carry[1 * CS + idx] = si;
        float Ar = g_csum[0 * CS + idx];
        float Ai = g_csum[1 * CS + idx];
        float br = g_csum[2 * CS + idx];
        float bi = g_csum[3 * CS + idx];
        float d  = g_csum[4 * CS + idx];
        if (d != 0.0f) { sr = br; si = bi; }
        else {
            float ns = Ar * sr - Ai * si + br;
            si = Ar * si + Ai * sr + bi; sr = ns;
        }
    }
}

__global__ void scan_p3() {
    int tg = blockIdx.x * blockDim.x + threadIdx.x;
    if (tg >= CS) return;
    int h = tg & 255;
    int b = (tg >> 8) & 15;
    int c = tg >> 12;
    int idx = c * 4096 + b * 256 + h;
    float lr = g_lam[h], li = g_lam[H_DIM + h];
    float sr = g_carry[0 * CS + idx];
    float si = g_carry[1 * CS + idx];
    int t0 = c * LCH;
    for (int t = t0; t < t0 + LCH; t++) {
        int row = t * B_DIM + b;
        float* p = g_Bu + (long long)row * N1;
        float ur = p[h], ui = p[H_DIM + h];
        if (g_flags[row]) { sr = ur; si = ui; }
        else {
            float ns = lr * sr - li * si + ur;
            si = lr * si + li * sr + ui; sr = ns;
        }
        p[h] = sr;
        p[H_DIM + h] = si;
    }
}

// -------- launch --------
extern "C" void kernel_launch(void* const* d_in, const int* in_sizes, int n_in,
                              void* d_out, int out_size) {
    const float* x        = (const float*)d_in[0];
    const void*  starts   = d_in[1];
    const float* state_re = (const float*)d_in[2];
    const float* state_im = (const float*)d_in[3];
    const float* nu_log   = (const float*)d_in[4];
    const float* theta_log= (const float*)d_in[5];
    const float* B_re     = (const float*)d_in[6];
    const float* B_im     = (const float*)d_in[7];
    const float* C_re     = (const float*)d_in[8];
    const float* C_im     = (const float*)d_in[9];
    const float* Dvec     = (const float*)d_in[10];
    float* out = (float*)d_out;

    // Resolve device addresses of __device__ globals (host-side symbol names
    // are shadow variables — MUST go through cudaGetSymbolAddress).
    float *Bu_p = nullptr, *GB_p = nullptr, *CC_p = nullptr;
    cudaGetSymbolAddress((void**)&Bu_p, g_Bu);
    cudaGetSymbolAddress((void**)&GB_p, g_GB);
    cudaGetSymbolAddress((void**)&CC_p, g_CC);

    // starts dtype detection + flag conversion
    k_detect<<<1, 1024>>>((const unsigned char*)starts, M_DIM);
    k_flags<<<M_DIM / 256, 256>>>(starts);

    // parameter prep
    k_lam<<<1, 256>>>(nu_log, theta_log);
    k_gb<<<(N1 * D_DIM) / 256, 256>>>(B_re, B_im);
    k_cc<<<(D_DIM * N1) / 256, 256>>>(C_re, C_im);

    // GEMM1: Bu[M,512] = x[M,256] @ GB[512,256]^T
    {
        dim3 grid(N1 / BN, M_DIM / BM);
        sgemm_nt<<<grid, 256>>>(x, GB_p, Bu_p, M_DIM, N1, D_DIM, nullptr, nullptr);
    }

    // segmented scan (in place on g_Bu)
    scan_p1<<<CS / 256, 256>>>();
    scan_p2<<<(B_DIM * H_DIM) / 256, 256>>>(state_re, state_im);
    scan_p3<<<CS / 256, 256>>>();

    // GEMM3: out[M,256] = h[M,512] @ CC[256,512]^T + D*x
    {
        dim3 grid(D_DIM / BN, M_DIM / BM);
        sgemm_nt<<<grid, 256>>>(Bu_p, CC_p, out, M_DIM, D_DIM, 2 * H_DIM, Dvec, x);
    }
}

// round 4
// speedup vs baseline: 1.6760x; 1.6760x over previous
#include <cuda_runtime.h>
#include <cuda_bf16.h>
#include <math.h>
#include <stdint.h>

// Problem dims
#define T_DIM 4096
#define B_DIM 16
#define H_DIM 256
#define D_DIM 256
#define M_DIM (T_DIM * B_DIM)        // 65536
#define N1 (2 * H_DIM)               // 512
#define NCHUNK 32
#define LCH (T_DIM / NCHUNK)         // 128
#define CS (NCHUNK * B_DIM * H_DIM)  // 131072

// -------- device scratch --------
__device__ float g_Bu[(size_t)M_DIM * N1];            // Bu fp32 (GEMM1 out, scan in)
__device__ __nv_bfloat16 g_A1[(size_t)M_DIM * 512];   // [x_hi | x_lo]
__device__ __nv_bfloat16 g_A3[(size_t)M_DIM * 1024];  // [h_re_hi, h_im_hi | h_re_lo, h_im_lo]
__device__ __nv_bfloat16 g_B1[512 * 768];             // [w_hi | w_hi | w_lo]
__device__ __nv_bfloat16 g_B3[256 * 1536];            // [c_hi | c_hi | c_lo]
__device__ float g_lam[2 * H_DIM];
__device__ float g_gamma[H_DIM];
__device__ unsigned char g_flags[M_DIM];
__device__ float g_csum[5 * CS];
__device__ float g_carry[2 * CS];
__device__ int g_mode;

// ================= helpers =================
__device__ __forceinline__ uint32_t smem_u32(const void* p) {
    uint32_t a;
    asm("{ .reg .u64 t; cvta.to.shared.u64 t, %1; cvt.u32.u64 %0, t; }" : "=r"(a) : "l"(p));
    return a;
}
#define SWZ128(o) ((o) ^ (((o) >> 3) & 0x70))

#define CP_ASYNC16(dst, src) asm volatile("cp.async.cg.shared.global [%0], [%1], 16;" :: "r"(dst), "l"(src))
#define CP_COMMIT()          asm volatile("cp.async.commit_group;")

__device__ __forceinline__ void ldsm4(uint32_t& r0, uint32_t& r1, uint32_t& r2, uint32_t& r3, uint32_t a) {
    asm volatile("ldmatrix.sync.aligned.m8n8.x4.shared.b16 {%0,%1,%2,%3}, [%4];"
                 : "=r"(r0), "=r"(r1), "=r"(r2), "=r"(r3) : "r"(a));
}

__device__ __forceinline__ void mma_bf16(float* d, const uint32_t* a, const uint32_t* b) {
    asm volatile(
        "mma.sync.aligned.m16n8k16.row.col.f32.bf16.bf16.f32 "
        "{%0,%1,%2,%3}, {%4,%5,%6,%7}, {%8,%9}, {%0,%1,%2,%3};"
        : "+f"(d[0]), "+f"(d[1]), "+f"(d[2]), "+f"(d[3])
        : "r"(a[0]), "r"(a[1]), "r"(a[2]), "r"(a[3]), "r"(b[0]), "r"(b[1]));
}

__device__ __forceinline__ void bf16_split(float v, __nv_bfloat16& hi, __nv_bfloat16& lo) {
    hi = __float2bfloat16_rn(v);
    lo = __float2bfloat16_rn(v - __bfloat162float(hi));
}

// ================= prep kernels =================
__global__ void k_detect(const unsigned char* __restrict__ s, int nbytes) {
    __shared__ int sh_gt1, sh_nm4;
    if (threadIdx.x == 0) { sh_gt1 = 0; sh_nm4 = 0; }
    __syncthreads();
    int gt1 = 0, nm4 = 0;
    for (int i = threadIdx.x; i < nbytes; i += blockDim.x) {
        unsigned char v = s[i];
        if (v > 1) gt1 = 1;
        if (v != 0 && (i & 3) != 0) nm4 = 1;
    }
    if (gt1) atomicOr(&sh_gt1, 1);
    if (nm4) atomicOr(&sh_nm4, 1);
    __syncthreads();
    if (threadIdx.x == 0) g_mode = sh_gt1 ? 2 : (sh_nm4 ? 0 : 1);
}

__global__ void k_flags(const void* __restrict__ s) {
    int i = blockIdx.x * blockDim.x + threadIdx.x;
    if (i >= M_DIM) return;
    int m = g_mode;
    unsigned char f;
    if (m == 0)       f = ((const unsigned char*)s)[i] != 0;
    else if (m == 1)  f = ((const int*)s)[i] != 0;
    else              f = ((const float*)s)[i] != 0.0f;
    g_flags[i] = f;
}

__global__ void k_lam(const float* __restrict__ nu_log, const float* __restrict__ theta_log) {
    int h = threadIdx.x;
    if (h >= H_DIM) return;
    float nu = expf(nu_log[h]);
    float th = expf(theta_log[h]);
    float mag = expf(-nu);
    g_lam[h] = mag * cosf(th);
    g_lam[H_DIM + h] = mag * sinf(th);
    g_gamma[h] = sqrtf(fmaxf(1.0f - mag * mag, 1e-8f));
}

__global__ void k_wb1(const float* __restrict__ B_re, const float* __restrict__ B_im) {
    int i = blockIdx.x * blockDim.x + threadIdx.x;  // 512*256
    if (i >= 512 * 256) return;
    int n = i >> 8, d = i & 255;
    int h = n & 255;
    float w = ((n < 256) ? B_re[h * 256 + d] : B_im[h * 256 + d]) * g_gamma[h];
    __nv_bfloat16 hi, lo; bf16_split(w, hi, lo);
    g_B1[(size_t)n * 768 + d] = hi;
    g_B1[(size_t)n * 768 + 256 + d] = hi;
    g_B1[(size_t)n * 768 + 512 + d] = lo;
}

__global__ void k_wb3(const float* __restrict__ C_re, const float* __restrict__ C_im) {
    int i = blockIdx.x * blockDim.x + threadIdx.x;  // 256*512
    if (i >= 256 * 512) return;
    int d = i >> 9, k = i & 511;
    float c = (k < 256) ? C_re[d * 256 + k] : -C_im[d * 256 + (k - 256)];
    __nv_bfloat16 hi, lo; bf16_split(c, hi, lo);
    g_B3[(size_t)d * 1536 + k] = hi;
    g_B3[(size_t)d * 1536 + 512 + k] = hi;
    g_B3[(size_t)d * 1536 + 1024 + k] = lo;
}

__global__ void k_splitx(const float* __restrict__ x) {
    int i = blockIdx.x * blockDim.x + threadIdx.x;  // M*256
    if (i >= M_DIM * 256) return;
    int m = i >> 8, d = i & 255;
    __nv_bfloat16 hi, lo; bf16_split(x[i], hi, lo);
    g_A1[(size_t)m * 512 + d] = hi;
    g_A1[(size_t)m * 512 + 256 + d] = lo;
}

// ================= mma.sync bf16 GEMM =================
// C[M,N] = A'[M,K'] @ B'[N,K']^T. A stored [M,lda]; chunk kc reads A cols
// ((kc<wrap)?kc:kc-wrap)*64, B cols kc*64. CTA tile 128x128, BK=64,
// 8 warps in 2(m)x4(n), warp tile 64x32. SW128 swizzled smem, 2-stage cp.async.
#define GSMEM (2 * 32768)

__global__ void __launch_bounds__(256) mma_gemm(
    const __nv_bfloat16* __restrict__ gA, int lda,
    const __nv_bfloat16* __restrict__ gB, int ldb,
    int NC, int wrap,
    float* __restrict__ C, int ldc,
    const float* __restrict__ Dv, const float* __restrict__ X)
{
    extern __shared__ char smem[];
    uint32_t sb = smem_u32(smem);
    int tid = threadIdx.x, lane = tid & 31, wid = tid >> 5;
    int warpm = wid & 1, warpn = wid >> 1;
    int bm = blockIdx.y, bn = blockIdx.x;

    const __nv_bfloat16* Abase = gA + (size_t)(bm * 128) * lda;
    const __nv_bfloat16* Bbase = gB + (size_t)(bn * 128) * ldb;

    float acc[4][4][4];
    #pragma unroll
    for (int i = 0; i < 4; i++)
        #pragma unroll
        for (int j = 0; j < 4; j++)
            #pragma unroll
            for (int q = 0; q < 4; q++) acc[i][j][q] = 0.0f;

    int lrow = tid >> 1;               // 0..127
    int lseg = (tid & 1) * 64;         // byte offset within 128B row

    // -------- stage loader --------
    #define LOAD_STAGE(kc, s) do {                                                     \
        int _acol = (((kc) < wrap) ? (kc) : (kc) - wrap) * 64;                         \
        int _bcol = (kc) * 64;                                                         \
        uint32_t _sA = sb + (s) * 32768;                                               \
        uint32_t _sB = _sA + 16384;                                                    \
        const char* _srcA = (const char*)(Abase + (size_t)lrow * lda + _acol) + lseg;  \
        const char* _srcB = (const char*)(Bbase + (size_t)lrow * ldb + _bcol) + lseg;  \
        _Pragma("unroll")                                                              \
        for (int _j = 0; _j < 4; _j++) {                                               \
            uint32_t _off = (uint32_t)lrow * 128 + lseg + _j * 16;                     \
            uint32_t _swo = SWZ128(_off);                                              \
            CP_ASYNC16(_sA + _swo, (const void*)__cvta_generic_to_global(_srcA + _j * 16)); \
            CP_ASYNC16(_sB + _swo, (const void*)__cvta_generic_to_global(_srcB + _j * 16)); \
        } } while (0)

    LOAD_STAGE(0, 0); CP_COMMIT();

    for (int kc = 0; kc < NC; kc++) {
        int s = kc & 1;
        if (kc + 1 < NC) {
            LOAD_STAGE(kc + 1, s ^ 1); CP_COMMIT();
            asm volatile("cp.async.wait_group 1;" ::: "memory");
        } else {
            asm volatile("cp.async.wait_group 0;" ::: "memory");
        }
        __syncthreads();

        uint32_t sA = sb + s * 32768, sB = sA + 16384;
        #pragma unroll
        for (int ks = 0; ks < 4; ks++) {
            int kb = ks * 32;
            uint32_t af[4][4], bf[4][2];
            #pragma unroll
            for (int mt = 0; mt < 4; mt++) {
                int row = warpm * 64 + mt * 16 + (lane & 15);
                uint32_t addr = sA + SWZ128((uint32_t)row * 128 + kb + (lane >> 4) * 16);
                ldsm4(af[mt][0], af[mt][1], af[mt][2], af[mt][3], addr);
            }
            #pragma unroll
            for (int np = 0; np < 2; np++) {
                int row = warpn * 32 + np * 16 + (lane & 15);
                uint32_t addr = sB + SWZ128((uint32_t)row * 128 + kb + (lane >> 4) * 16);
                uint32_t r0, r1, r2, r3;
                ldsm4(r0, r1, r2, r3, addr);
                bf[2 * np][0] = r0;     bf[2 * np][1] = r2;
                bf[2 * np + 1][0] = r1; bf[2 * np + 1][1] = r3;
            }
            #pragma unroll
            for (int mt = 0; mt < 4; mt++)
                #pragma unroll
                for (int nt = 0; nt < 4; nt++)
                    mma_bf16(acc[mt][nt], af[mt], bf[nt]);
        }
        __syncthreads();
    }

    // -------- epilogue --------
    int m0 = bm * 128 + warpm * 64;
    int n0 = bn * 128 + warpn * 32;
    int rq = lane >> 2, cq = (lane & 3) * 2;
    #pragma unroll
    for (int mt = 0; mt < 4; mt++) {
        #pragma unroll
        for (int h = 0; h < 2; h++) {
            int r = m0 + mt * 16 + h * 8 + rq;
            float* crow = C + (size_t)r * ldc;
            const float* xrow = X ? (X + (size_t)r * ldc) : nullptr;
            #pragma unroll
            for (int nt = 0; nt < 4; nt++) {
                int c = n0 + nt * 8 + cq;
                float v0 = acc[mt][nt][h * 2 + 0];
                float v1 = acc[mt][nt][h * 2 + 1];
                if (Dv) {
                    v0 = fmaf(Dv[c],     xrow[c],     v0);
                    v1 = fmaf(Dv[c + 1], xrow[c + 1], v1);
                }
                *(float2*)(crow + c) = make_float2(v0, v1);
            }
        }
    }
}

// ================= segmented scan =================
__global__ void scan_p1() {
    int tg = blockIdx.x * blockDim.x + threadIdx.x;
    if (tg >= CS) return;
    int h = tg & 255, b = (tg >> 8) & 15, c = tg >> 12;
    float lr = g_lam[h], li = g_lam[H_DIM + h];
    float Ar = 1.0f, Ai = 0.0f, br = 0.0f, bi = 0.0f, dAny = 0.0f;
    int t0 = c * LCH;
    for (int t = t0; t < t0 + LCH; t++) {
        int row = t * B_DIM + b;
        const float* p = g_Bu + (size_t)row * N1;
        float ur = p[h], ui = p[H_DIM + h];
        if (g_flags[row]) { Ar = lr; Ai = li; br = ur; bi = ui; dAny = 1.0f; }
        else {
            float nAr = lr * Ar - li * Ai;
            Ai = lr * Ai + li * Ar; Ar = nAr;
            float nbr = lr * br - li * bi + ur;
            bi = lr * bi + li * br + ui; br = nbr;
        }
    }
    int idx = c * 4096 + b * 256 + h;
    g_csum[0 * CS + idx] = Ar; g_csum[1 * CS + idx] = Ai;
    g_csum[2 * CS + idx] = br; g_csum[3 * CS + idx] = bi;
    g_csum[4 * CS + idx] = dAny;
}

__global__ void scan_p2(const float* __restrict__ st_re, const float* __restrict__ st_im) {
    int bh = blockIdx.x * blockDim.x + threadIdx.x;
    if (bh >= B_DIM * H_DIM) return;
    float sr = st_re[bh], si = st_im[bh];
    for (int c = 0; c < NCHUNK; c++) {
        int idx = c * 4096 + bh;
        g_carry[0 * CS + idx] = sr;
        g_carry[1 * CS + idx] = si;
        float Ar = g_csum[0 * CS + idx], Ai = g_csum[1 * CS + idx];
        float br = g_csum[2 * CS + idx], bi = g_csum[3 * CS + idx];
        float d  = g_csum[4 * CS + idx];
        if (d != 0.0f) { sr = br; si = bi; }
        else {
            float ns = Ar * sr - Ai * si + br;
            si = Ar * si + Ai * sr + bi; sr = ns;
        }
    }
}

// phase 3: recompute states, emit bf16 split directly into g_A3 [M, 1024]
__global__ void scan_p3() {
    int tg = blockIdx.x * blockDim.x + threadIdx.x;
    if (tg >= CS) return;
    int h = tg & 255, b = (tg >> 8) & 15, c = tg >> 12;
    int idx = c * 4096 + b * 256 + h;
    float lr = g_lam[h], li = g_lam[H_DIM + h];
    float sr = g_carry[0 * CS + idx], si = g_carry[1 * CS + idx];
    int t0 = c * LCH;
    for (int t = t0; t < t0 + LCH; t++) {
        int row = t * B_DIM + b;
        const float* p = g_Bu + (size_t)row * N1;
        float ur = p[h], ui = p[H_DIM + h];
        if (g_flags[row]) { sr = ur; si = ui; }
        else {
            float ns = lr * sr - li * si + ur;
            si = lr * si + li * sr + ui; sr = ns;
        }
        __nv_bfloat16 hr, lr2, hi2, li2;
        bf16_split(sr, hr, lr2);
        bf16_split(si, hi2, li2);
        __nv_bfloat16* q = g_A3 + (size_t)row * 1024;
        q[h] = hr;
        q[256 + h] = hi2;
        q[512 + h] = lr2;
        q[768 + h] = li2;
    }
}

// ================= launch =================
extern "C" void kernel_launch(void* const* d_in, const int* in_sizes, int n_in,
                              void* d_out, int out_size) {
    const float* x        = (const float*)d_in[0];
    const void*  starts   = d_in[1];
    const float* state_re = (const float*)d_in[2];
    const float* state_im = (const float*)d_in[3];
    const float* nu_log   = (const float*)d_in[4];
    const float* theta_log= (const float*)d_in[5];
    const float* B_re     = (const float*)d_in[6];
    const float* B_im     = (const float*)d_in[7];
    const float* C_re     = (const float*)d_in[8];
    const float* C_im     = (const float*)d_in[9];
    const float* Dvec     = (const float*)d_in[10];
    float* out = (float*)d_out;

    float* Bu_p; __nv_bfloat16 *A1_p, *A3_p, *B1_p, *B3_p;
    cudaGetSymbolAddress((void**)&Bu_p, g_Bu);
    cudaGetSymbolAddress((void**)&A1_p, g_A1);
    cudaGetSymbolAddress((void**)&A3_p, g_A3);
    cudaGetSymbolAddress((void**)&B1_p, g_B1);
    cudaGetSymbolAddress((void**)&B3_p, g_B3);

    cudaFuncSetAttribute(mma_gemm, cudaFuncAttributeMaxDynamicSharedMemorySize, GSMEM);

    k_detect<<<1, 1024>>>((const unsigned char*)starts, M_DIM);
    k_flags<<<M_DIM / 256, 256>>>(starts);
    k_lam<<<1, 256>>>(nu_log, theta_log);
    k_wb1<<<(512 * 256) / 256, 256>>>(B_re, B_im);
    k_wb3<<<(256 * 512) / 256, 256>>>(C_re, C_im);
    k_splitx<<<(M_DIM * 256) / 256, 256>>>(x);

    // GEMM1: Bu[M,512] = [x_hi|x_lo] @ B1^T, K'=768, wrap=8
    {
        dim3 grid(512 / 128, M_DIM / 128);
        mma_gemm<<<grid, 256, GSMEM>>>(A1_p, 512, B1_p, 768, 12, 8,
                                       Bu_p, 512, nullptr, nullptr);
    }

    scan_p1<<<CS / 256, 256>>>();
    scan_p2<<<(B_DIM * H_DIM) / 256, 256>>>(state_re, state_im);
    scan_p3<<<CS / 256, 256>>>();

    // GEMM3: out[M,256] = [h_hi|h_lo] @ B3^T + D*x, K'=1536, wrap=16
    {
        dim3 grid(256 / 128, M_DIM / 128);
        mma_gemm<<<grid, 256, GSMEM>>>(A3_p, 1024, B3_p, 1536, 24, 16,
                                       out, 256, Dvec, x);
    }
}

// round 5
// speedup vs baseline: 1.8557x; 1.1072x over previous
#include <cuda_runtime.h>
#include <cuda_fp16.h>
#include <math.h>
#include <stdint.h>

// Problem dims
#define T_DIM 4096
#define B_DIM 16
#define H_DIM 256
#define D_DIM 256
#define M_DIM (T_DIM * B_DIM)        // 65536
#define N1 (2 * H_DIM)               // 512
#define NCHUNK 32
#define LCH (T_DIM / NCHUNK)         // 128
#define CS (NCHUNK * B_DIM * H_DIM)  // 131072

// -------- device scratch --------
__device__ float g_Bu[(size_t)M_DIM * N1];       // Bu fp32 (GEMM1 out, scan in)
__device__ __half g_A1[(size_t)M_DIM * 512];     // [x_hi | x_lo] fp16
__device__ __half g_A3[(size_t)M_DIM * 512];     // [h_re | h_im] fp16 (single)
__device__ __half g_B1[512 * 768];               // [w_hi | w_hi | w_lo]
__device__ __half g_B3[256 * 1024];              // [c_hi | c_lo]
__device__ float g_lam[2 * H_DIM];
__device__ float g_gamma[H_DIM];
__device__ unsigned char g_flags[M_DIM];
__device__ float g_csum[5 * CS];
__device__ float g_carry[2 * CS];
__device__ int g_mode;

// ================= helpers =================
__device__ __forceinline__ uint32_t smem_u32(const void* p) {
    uint32_t a;
    asm("{ .reg .u64 t; cvta.to.shared.u64 t, %1; cvt.u32.u64 %0, t; }" : "=r"(a) : "l"(p));
    return a;
}
#define SWZ128(o) ((o) ^ (((o) >> 3) & 0x70))

#define CP_ASYNC16(dst, src) asm volatile("cp.async.cg.shared.global [%0], [%1], 16;" :: "r"(dst), "l"(src))
#define CP_COMMIT()          asm volatile("cp.async.commit_group;")

__device__ __forceinline__ void ldsm4(uint32_t& r0, uint32_t& r1, uint32_t& r2, uint32_t& r3, uint32_t a) {
    asm volatile("ldmatrix.sync.aligned.m8n8.x4.shared.b16 {%0,%1,%2,%3}, [%4];"
                 : "=r"(r0), "=r"(r1), "=r"(r2), "=r"(r3) : "r"(a));
}

__device__ __forceinline__ void mma_f16(float* d, const uint32_t* a, const uint32_t* b) {
    asm volatile(
        "mma.sync.aligned.m16n8k16.row.col.f32.f16.f16.f32 "
        "{%0,%1,%2,%3}, {%4,%5,%6,%7}, {%8,%9}, {%0,%1,%2,%3};"
        : "+f"(d[0]), "+f"(d[1]), "+f"(d[2]), "+f"(d[3])
        : "r"(a[0]), "r"(a[1]), "r"(a[2]), "r"(a[3]), "r"(b[0]), "r"(b[1]));
}

__device__ __forceinline__ void h16_split(float v, __half& hi, __half& lo) {
    hi = __float2half_rn(v);
    lo = __float2half_rn(v - __half2float(hi));
}

// ================= prep kernels =================
__global__ void k_detect(const unsigned char* __restrict__ s, int nbytes) {
    __shared__ int sh_gt1, sh_nm4;
    if (threadIdx.x == 0) { sh_gt1 = 0; sh_nm4 = 0; }
    __syncthreads();
    int gt1 = 0, nm4 = 0;
    for (int i = threadIdx.x; i < nbytes; i += blockDim.x) {
        unsigned char v = s[i];
        if (v > 1) gt1 = 1;
        if (v != 0 && (i & 3) != 0) nm4 = 1;
    }
    if (gt1) atomicOr(&sh_gt1, 1);
    if (nm4) atomicOr(&sh_nm4, 1);
    __syncthreads();
    if (threadIdx.x == 0) g_mode = sh_gt1 ? 2 : (sh_nm4 ? 0 : 1);
}

__global__ void k_flags(const void* __restrict__ s) {
    int i = blockIdx.x * blockDim.x + threadIdx.x;
    if (i >= M_DIM) return;
    int m = g_mode;
    unsigned char f;
    if (m == 0)       f = ((const unsigned char*)s)[i] != 0;
    else if (m == 1)  f = ((const int*)s)[i] != 0;
    else              f = ((const float*)s)[i] != 0.0f;
    g_flags[i] = f;
}

__global__ void k_lam(const float* __restrict__ nu_log, const float* __restrict__ theta_log) {
    int h = threadIdx.x;
    if (h >= H_DIM) return;
    float nu = expf(nu_log[h]);
    float th = expf(theta_log[h]);
    float mag = expf(-nu);
    g_lam[h] = mag * cosf(th);
    g_lam[H_DIM + h] = mag * sinf(th);
    g_gamma[h] = sqrtf(fmaxf(1.0f - mag * mag, 1e-8f));
}

__global__ void k_wb1(const float* __restrict__ B_re, const float* __restrict__ B_im) {
    int i = blockIdx.x * blockDim.x + threadIdx.x;  // 512*256
    if (i >= 512 * 256) return;
    int n = i >> 8, d = i & 255;
    int h = n & 255;
    float w = ((n < 256) ? B_re[h * 256 + d] : B_im[h * 256 + d]) * g_gamma[h];
    __half hi, lo; h16_split(w, hi, lo);
    g_B1[(size_t)n * 768 + d] = hi;
    g_B1[(size_t)n * 768 + 256 + d] = hi;
    g_B1[(size_t)n * 768 + 512 + d] = lo;
}

__global__ void k_wb3(const float* __restrict__ C_re, const float* __restrict__ C_im) {
    int i = blockIdx.x * blockDim.x + threadIdx.x;  // 256*512
    if (i >= 256 * 512) return;
    int d = i >> 9, k = i & 511;
    float c = (k < 256) ? C_re[d * 256 + k] : -C_im[d * 256 + (k - 256)];
    __half hi, lo; h16_split(c, hi, lo);
    g_B3[(size_t)d * 1024 + k] = hi;
    g_B3[(size_t)d * 1024 + 512 + k] = lo;
}

__global__ void k_splitx(const float* __restrict__ x) {
    int i = blockIdx.x * blockDim.x + threadIdx.x;  // M*256
    if (i >= M_DIM * 256) return;
    int m = i >> 8, d = i & 255;
    __half hi, lo; h16_split(x[i], hi, lo);
    g_A1[(size_t)m * 512 + d] = hi;
    g_A1[(size_t)m * 512 + 256 + d] = lo;
}

// ================= mma.sync fp16 GEMM =================
// C[M,N] = A'[M,K'] @ B'[N,K']^T. Chunk kc reads A cols ((kc<wrap)?kc:kc-wrap)*64,
// B cols kc*64. CTA tile 128x128, BK=64, 8 warps (2m x 4n), warp tile 64x32.
// SW128 swizzled smem, 3-stage cp.async pipeline (always-commit; wait_group 2).
#define GSMEM (3 * 32768)

__global__ void __launch_bounds__(256, 2) mma_gemm(
    const __half* __restrict__ gA, int lda,
    const __half* __restrict__ gB, int ldb,
    int NC, int wrap,
    float* __restrict__ C, int ldc,
    const float* __restrict__ Dv, const float* __restrict__ X)
{
    extern __shared__ char smem[];
    uint32_t sb = smem_u32(smem);
    int tid = threadIdx.x, lane = tid & 31, wid = tid >> 5;
    int warpm = wid & 1, warpn = wid >> 1;
    int bm = blockIdx.y, bn = blockIdx.x;

    const __half* Abase = gA + (size_t)(bm * 128) * lda;
    const __half* Bbase = gB + (size_t)(bn * 128) * ldb;

    float acc[4][4][4];
    #pragma unroll
    for (int i = 0; i < 4; i++)
        #pragma unroll
        for (int j = 0; j < 4; j++)
            #pragma unroll
            for (int q = 0; q < 4; q++) acc[i][j][q] = 0.0f;

    int lrow = tid >> 1;               // 0..127
    int lseg = (tid & 1) * 64;         // byte offset within 128B row

    #define LOAD_STAGE(kc, s) do {                                                     \
        int _acol = (((kc) < wrap) ? (kc) : (kc) - wrap) * 64;                         \
        int _bcol = (kc) * 64;                                                         \
        uint32_t _sA = sb + (s) * 32768;                                               \
        uint32_t _sB = _sA + 16384;                                                    \
        const char* _srcA = (const char*)(Abase + (size_t)lrow * lda + _acol) + lseg;  \
        const char* _srcB = (const char*)(Bbase + (size_t)lrow * ldb + _bcol) + lseg;  \
        _Pragma("unroll")                                                              \
        for (int _j = 0; _j < 4; _j++) {                                               \
            uint32_t _off = (uint32_t)lrow * 128 + lseg + _j * 16;                     \
            uint32_t _swo = SWZ128(_off);                                              \
            CP_ASYNC16(_sA + _swo, (const void*)__cvta_generic_to_global(_srcA + _j * 16)); \
            CP_ASYNC16(_sB + _swo, (const void*)__cvta_generic_to_global(_srcB + _j * 16)); \
        } } while (0)

    LOAD_STAGE(0, 0); CP_COMMIT();
    LOAD_STAGE(1, 1); CP_COMMIT();

    for (int kc = 0; kc < NC; kc++) {
        int s = kc % 3;
        __syncthreads();                        // prior stage reads done before overwrite
        if (kc + 2 < NC) {
            int s2 = (kc + 2) % 3;
            LOAD_STAGE(kc + 2, s2);
        }
        CP_COMMIT();                            // always commit (empty group ok)
        asm volatile("cp.async.wait_group 2;" ::: "memory");
        __syncthreads();                        // group kc visible to all warps

        uint32_t sA = sb + s * 32768, sB = sA + 16384;
        #pragma unroll
        for (int ks = 0; ks < 4; ks++) {
            int kb = ks * 32;
            uint32_t af[4][4], bf[4][2];
            #pragma unroll
            for (int mt = 0; mt < 4; mt++) {
                int row = warpm * 64 + mt * 16 + (lane & 15);
                uint32_t addr = sA + SWZ128((uint32_t)row * 128 + kb + (lane >> 4) * 16);
                ldsm4(af[mt][0], af[mt][1], af[mt][2], af[mt][3], addr);
            }
            #pragma unroll
            for (int np = 0; np < 2; np++) {
                int row = warpn * 32 + np * 16 + (lane & 15);
                uint32_t addr = sB + SWZ128((uint32_t)row * 128 + kb + (lane >> 4) * 16);
                uint32_t r0, r1, r2, r3;
                ldsm4(r0, r1, r2, r3, addr);
                bf[2 * np][0] = r0;     bf[2 * np][1] = r2;
                bf[2 * np + 1][0] = r1; bf[2 * np + 1][1] = r3;
            }
            #pragma unroll
            for (int mt = 0; mt < 4; mt++)
                #pragma unroll
                for (int nt = 0; nt < 4; nt++)
                    mma_f16(acc[mt][nt], af[mt], bf[nt]);
        }
    }

    // -------- epilogue --------
    int m0 = bm * 128 + warpm * 64;
    int n0 = bn * 128 + warpn * 32;
    int rq = lane >> 2, cq = (lane & 3) * 2;
    #pragma unroll
    for (int mt = 0; mt < 4; mt++) {
        #pragma unroll
        for (int h = 0; h < 2; h++) {
            int r = m0 + mt * 16 + h * 8 + rq;
            float* crow = C + (size_t)r * ldc;
            const float* xrow = X ? (X + (size_t)r * ldc) : nullptr;
            #pragma unroll
            for (int nt = 0; nt < 4; nt++) {
                int c = n0 + nt * 8 + cq;
                float v0 = acc[mt][nt][h * 2 + 0];
                float v1 = acc[mt][nt][h * 2 + 1];
                if (Dv) {
                    v0 = fmaf(Dv[c],     xrow[c],     v0);
                    v1 = fmaf(Dv[c + 1], xrow[c + 1], v1);
                }
                *(float2*)(crow + c) = make_float2(v0, v1);
            }
        }
    }
}

// ================= segmented scan =================
__global__ void scan_p1() {
    int tg = blockIdx.x * blockDim.x + threadIdx.x;
    if (tg >= CS) return;
    int h = tg & 255, b = (tg >> 8) & 15, c = tg >> 12;
    float lr = g_lam[h], li = g_lam[H_DIM + h];
    float Ar = 1.0f, Ai = 0.0f, br = 0.0f, bi = 0.0f, dAny = 0.0f;
    int t0 = c * LCH;
    for (int t = t0; t < t0 + LCH; t++) {
        int row = t * B_DIM + b;
        const float* p = g_Bu + (size_t)row * N1;
        float ur = p[h], ui = p[H_DIM + h];
        if (g_flags[row]) { Ar = lr; Ai = li; br = ur; bi = ui; dAny = 1.0f; }
        else {
            float nAr = lr * Ar - li * Ai;
            Ai = lr * Ai + li * Ar; Ar = nAr;
            float nbr = lr * br - li * bi + ur;
            bi = lr * bi + li * br + ui; br = nbr;
        }
    }
    int idx = c * 4096 + b * 256 + h;
    g_csum[0 * CS + idx] = Ar; g_csum[1 * CS + idx] = Ai;
    g_csum[2 * CS + idx] = br; g_csum[3 * CS + idx] = bi;
    g_csum[4 * CS + idx] = dAny;
}

__global__ void scan_p2(const float* __restrict__ st_re, const float* __restrict__ st_im) {
    int bh = blockIdx.x * blockDim.x + threadIdx.x;
    if (bh >= B_DIM * H_DIM) return;
    float sr = st_re[bh], si = st_im[bh];
    for (int c = 0; c < NCHUNK; c++) {
        int idx = c * 4096 + bh;
        g_carry[0 * CS + idx] = sr;
        g_carry[1 * CS + idx] = si;
        float Ar = g_csum[0 * CS + idx], Ai = g_csum[1 * CS + idx];
        float br = g_csum[2 * CS + idx], bi = g_csum[3 * CS + idx];
        float d  = g_csum[4 * CS + idx];
        if (d != 0.0f) { sr = br; si = bi; }
        else {
            float ns = Ar * sr - Ai * si + br;
            si = Ar * si + Ai * sr + bi; sr = ns;
        }
    }
}

// phase 3: recompute states, emit fp16 h directly into g_A3 [M, 512]
__global__ void scan_p3() {
    int tg = blockIdx.x * blockDim.x + threadIdx.x;
    if (tg >= CS) return;
    int h = tg & 255, b = (tg >> 8) & 15, c = tg >> 12;
    int idx = c * 4096 + b * 256 + h;
    float lr = g_lam[h], li = g_lam[H_DIM + h];
    float sr = g_carry[0 * CS + idx], si = g_carry[1 * CS + idx];
    int t0 = c * LCH;
    for (int t = t0; t < t0 + LCH; t++) {
        int row = t * B_DIM + b;
        const float* p = g_Bu + (size_t)row * N1;
        float ur = p[h], ui = p[H_DIM + h];
        if (g_flags[row]) { sr = ur; si = ui; }
        else {
            float ns = lr * sr - li * si + ur;
            si = lr * si + li * sr + ui; sr = ns;
        }
        __half* q = g_A3 + (size_t)row * 512;
        q[h] = __float2half_rn(sr);
        q[256 + h] = __float2half_rn(si);
    }
}

// ================= launch =================
extern "C" void kernel_launch(void* const* d_in, const int* in_sizes, int n_in,
                              void* d_out, int out_size) {
    const float* x        = (const float*)d_in[0];
    const void*  starts   = d_in[1];
    const float* state_re = (const float*)d_in[2];
    const float* state_im = (const float*)d_in[3];
    const float* nu_log   = (const float*)d_in[4];
    const float* theta_log= (const float*)d_in[5];
    const float* B_re     = (const float*)d_in[6];
    const float* B_im     = (const float*)d_in[7];
    const float* C_re     = (const float*)d_in[8];
    const float* C_im     = (const float*)d_in[9];
    const float* Dvec     = (const float*)d_in[10];
    float* out = (float*)d_out;

    float* Bu_p; __half *A1_p, *A3_p, *B1_p, *B3_p;
    cudaGetSymbolAddress((void**)&Bu_p, g_Bu);
    cudaGetSymbolAddress((void**)&A1_p, g_A1);
    cudaGetSymbolAddress((void**)&A3_p, g_A3);
    cudaGetSymbolAddress((void**)&B1_p, g_B1);
    cudaGetSymbolAddress((void**)&B3_p, g_B3);

    cudaFuncSetAttribute(mma_gemm, cudaFuncAttributeMaxDynamicSharedMemorySize, GSMEM);

    k_detect<<<1, 1024>>>((const unsigned char*)starts, M_DIM);
    k_flags<<<M_DIM / 256, 256>>>(starts);
    k_lam<<<1, 256>>>(nu_log, theta_log);
    k_wb1<<<(512 * 256) / 256, 256>>>(B_re, B_im);
    k_wb3<<<(256 * 512) / 256, 256>>>(C_re, C_im);
    k_splitx<<<(M_DIM * 256) / 256, 256>>>(x);

    // GEMM1: Bu[M,512] = [x_hi|x_lo] @ [w_hi|w_hi|w_lo]^T, K'=768, wrap=8
    {
        dim3 grid(512 / 128, M_DIM / 128);
        mma_gemm<<<grid, 256, GSMEM>>>(A1_p, 512, B1_p, 768, 12, 8,
                                       Bu_p, 512, nullptr, nullptr);
    }

    scan_p1<<<CS / 256, 256>>>();
    scan_p2<<<(B_DIM * H_DIM) / 256, 256>>>(state_re, state_im);
    scan_p3<<<CS / 256, 256>>>();

    // GEMM3: out[M,256] = h @ [c_hi|c_lo]^T + D*x, K'=1024, wrap=8
    {
        dim3 grid(256 / 128, M_DIM / 128);
        mma_gemm<<<grid, 256, GSMEM>>>(A3_p, 512, B3_p, 1024, 16, 8,
                                       out, 256, Dvec, x);
    }
}